// round 10
// baseline (speedup 1.0000x reference)
#include <cuda_runtime.h>
#include <mma.h>
#include <cuda_fp16.h>
#include <cstdint>
#include <math.h>

using namespace nvcuda;

// Problem constants
constexpr int Bb = 2, Ss = 2048, Ee = 4096, Hh = 16, Dd = 256, Rr = 64;
constexpr int Mtot = Bb * Ss;                  // 4096
constexpr size_t QK_ELEMS = (size_t)Bb * Hh * Ss * Dd;   // 16777216

// Shared tiling constants
constexpr int BM = 128, BK = 64;               // BK=64 halves = 128 bytes/row
constexpr int ASTR = BK + 8;                   // 72 halves = 144 B/row

// Scores tiling: CTA 128x128, 256 threads, 8 warps (2x4), warp 64x32, 2 CTAs/SM
constexpr int SBN = 128;
constexpr int SNT = 256;
constexpr uint32_t S_STAGE_A = BM * ASTR * 2;              // 18432
constexpr uint32_t S_STAGE = 2 * S_STAGE_A;                // 36864
constexpr int SCSTR = SBN + 4;                             // 132
constexpr uint32_t SCORES_SMEM = 2 * S_STAGE;              // 73728

// Proj tiling: CTA 128x256, 512 threads, 16 warps (2x8), warp 64x32, 1 CTA/SM
constexpr int PBN = 256;
constexpr int PNT = 512;
constexpr uint32_t P_STAGE_A = BM * ASTR * 2;              // 18432
constexpr uint32_t P_STAGE_B = PBN * ASTR * 2;             // 36864
constexpr uint32_t P_STAGE = P_STAGE_A + P_STAGE_B;        // 55296
constexpr int PCSTR = PBN + 4;                             // 260
constexpr uint32_t P_CS_BYTES = BM * PCSTR * 4;            // 133120
constexpr uint32_t PROJ_SMEM = P_CS_BYTES > 2 * P_STAGE ? P_CS_BYTES : 2 * P_STAGE;  // 133120

// Scratch (fp16 GEMM operands)
__device__ __half g_xnorm[(size_t)Mtot * Ee];
__device__ __half g_wq[(size_t)Ee * Ee];
__device__ __half g_wk[(size_t)Ee * Ee];
__device__ __half g_qr[QK_ELEMS];
__device__ __half g_kr[QK_ELEMS];

__device__ __forceinline__ uint32_t smem_u32(const void* p) {
    uint32_t a;
    asm("{ .reg .u64 t; cvta.to.shared.u64 t, %1; cvt.u32.u64 %0, t; }" : "=r"(a) : "l"(p));
    return a;
}
__device__ __forceinline__ void cp16(uint32_t dst, const void* src) {
    asm volatile("cp.async.cg.shared.global [%0], [%1], 16;" :: "r"(dst), "l"(src));
}
#define CP_COMMIT() asm volatile("cp.async.commit_group;" ::: "memory")
#define CP_WAIT1()  asm volatile("cp.async.wait_group 1;" ::: "memory")

using AccFrag = wmma::fragment<wmma::accumulator, 16, 16, 16, float>;
using AFrag = wmma::fragment<wmma::matrix_a, 16, 16, 16, __half, wmma::row_major>;
using BFrag = wmma::fragment<wmma::matrix_b, 16, 16, 16, __half, wmma::col_major>;

// ---------------------------------------------------------------------------
// LayerNorm -> fp16 g_xnorm
// ---------------------------------------------------------------------------
__global__ void __launch_bounds__(256) ln_kernel(const float* __restrict__ x,
                                                 const float* __restrict__ w,
                                                 const float* __restrict__ b) {
    int row = blockIdx.x;
    int tid = threadIdx.x;
    const float4* xr = reinterpret_cast<const float4*>(x + (size_t)row * Ee);

    float4 v[4];
    float sum = 0.f, ssq = 0.f;
#pragma unroll
    for (int j = 0; j < 4; j++) {
        v[j] = xr[tid + j * 256];
        sum += v[j].x + v[j].y + v[j].z + v[j].w;
        ssq += v[j].x * v[j].x + v[j].y * v[j].y + v[j].z * v[j].z + v[j].w * v[j].w;
    }
    __shared__ float s_sum[8], s_ssq[8];
#pragma unroll
    for (int o = 16; o; o >>= 1) {
        sum += __shfl_xor_sync(~0u, sum, o);
        ssq += __shfl_xor_sync(~0u, ssq, o);
    }
    if ((tid & 31) == 0) { s_sum[tid >> 5] = sum; s_ssq[tid >> 5] = ssq; }
    __syncthreads();
    if (tid < 32) {
        float ts = (tid < 8) ? s_sum[tid] : 0.f;
        float tq = (tid < 8) ? s_ssq[tid] : 0.f;
#pragma unroll
        for (int o = 4; o; o >>= 1) {
            ts += __shfl_xor_sync(~0u, ts, o);
            tq += __shfl_xor_sync(~0u, tq, o);
        }
        if (tid == 0) { s_sum[0] = ts; s_ssq[0] = tq; }
    }
    __syncthreads();
    float mean = s_sum[0] * (1.0f / Ee);
    float var = s_ssq[0] * (1.0f / Ee) - mean * mean;
    float rstd = rsqrtf(var + 1e-5f);

    const float4* wr = reinterpret_cast<const float4*>(w);
    const float4* br = reinterpret_cast<const float4*>(b);
    __half2* outr = reinterpret_cast<__half2*>(g_xnorm + (size_t)row * Ee);
#pragma unroll
    for (int j = 0; j < 4; j++) {
        int c = tid + j * 256;
        float4 wv = wr[c], bv = br[c];
        float o0 = (v[j].x - mean) * rstd * wv.x + bv.x;
        float o1 = (v[j].y - mean) * rstd * wv.y + bv.y;
        float o2 = (v[j].z - mean) * rstd * wv.z + bv.z;
        float o3 = (v[j].w - mean) * rstd * wv.w + bv.w;
        outr[c * 2]     = __floats2half2_rn(o0, o1);
        outr[c * 2 + 1] = __floats2half2_rn(o2, o3);
    }
}

// ---------------------------------------------------------------------------
// Weight conversion fp32 -> fp16
// ---------------------------------------------------------------------------
__global__ void __launch_bounds__(256) wconv_kernel(const float* __restrict__ wq,
                                                    const float* __restrict__ wk) {
    const float* src = blockIdx.y ? wk : wq;
    __half* dst = blockIdx.y ? g_wk : g_wq;
    size_t i = ((size_t)blockIdx.x * 256 + threadIdx.x) * 4;
    float4 v = *reinterpret_cast<const float4*>(src + i);
    __half2* d2 = reinterpret_cast<__half2*>(dst + i);
    d2[0] = __floats2half2_rn(v.x, v.y);
    d2[1] = __floats2half2_rn(v.z, v.w);
}

// ---------------------------------------------------------------------------
// Projection GEMM: CTA 128x256, 512 threads, warp tile 64x32, 2-stage pipeline
// ---------------------------------------------------------------------------
__device__ __forceinline__ void p_load_chunk(uint32_t sb, const char* Ab, const char* Bbp,
                                             int kc, int buf, int tid) {
    uint32_t stA = sb + buf * P_STAGE;
    uint32_t stB = stA + P_STAGE_A;
    const char* Ap = Ab + (size_t)kc * (BK * 2);
    const char* Bp = Bbp + (size_t)kc * (BK * 2);
#pragma unroll
    for (int l = 0; l < 2; l++) {                 // A: 128 rows x 8 x 16B
        int idx = tid + l * PNT;
        int r = idx >> 3, cb = (idx & 7) << 4;
        cp16(stA + r * (ASTR * 2) + cb, Ap + (size_t)r * (Ee * 2) + cb);
    }
#pragma unroll
    for (int l = 0; l < 4; l++) {                 // B: 256 rows x 8 x 16B
        int idx = tid + l * PNT;
        int r = idx >> 3, cb = (idx & 7) << 4;
        cp16(stB + r * (ASTR * 2) + cb, Bp + (size_t)r * (Ee * 2) + cb);
    }
}

__global__ void __launch_bounds__(PNT, 1) proj_cp_kernel(
    const float* __restrict__ bq, const float* __restrict__ bk,
    const float* __restrict__ embed, const int* __restrict__ posids,
    float* __restrict__ qout, float* __restrict__ kout)
{
    extern __shared__ __align__(128) char smem[];
    uint32_t sb = smem_u32(smem);
    int z = blockIdx.z;
    const __half* W   = z ? g_wk : g_wq;
    const float* bias = z ? bk : bq;
    float* outp       = z ? kout : qout;
    __half* routp     = z ? g_kr : g_qr;
    const int m0 = blockIdx.x * BM;
    const int n0 = blockIdx.y * PBN;
    int tid = threadIdx.x;
    int warp = tid >> 5;
    int wm = warp & 1;        // 2 along M (64 rows)
    int wn = warp >> 1;       // 8 along N (32 cols)

    const char* Ab = reinterpret_cast<const char*>(g_xnorm + (size_t)m0 * Ee);
    const char* Bbp = reinterpret_cast<const char*>(W + (size_t)n0 * Ee);

    AccFrag acc[4][2];
#pragma unroll
    for (int i = 0; i < 4; i++)
#pragma unroll
        for (int j = 0; j < 2; j++)
            wmma::fill_fragment(acc[i][j], 0.f);

    p_load_chunk(sb, Ab, Bbp, 0, 0, tid);
    CP_COMMIT();

    constexpr int NCHUNK = Ee / BK;   // 64
    for (int k = 0; k < NCHUNK; k++) {
        if (k + 1 < NCHUNK) p_load_chunk(sb, Ab, Bbp, k + 1, (k + 1) & 1, tid);
        CP_COMMIT();
        CP_WAIT1();
        __syncthreads();

        __half* As = reinterpret_cast<__half*>(smem + (k & 1) * P_STAGE);
        __half* Bs = As + BM * ASTR;
#pragma unroll
        for (int kk = 0; kk < BK; kk += 16) {
            AFrag af[4];
            BFrag bf[2];
#pragma unroll
            for (int i = 0; i < 4; i++)
                wmma::load_matrix_sync(af[i], As + (wm * 64 + i * 16) * ASTR + kk, ASTR);
#pragma unroll
            for (int j = 0; j < 2; j++)
                wmma::load_matrix_sync(bf[j], Bs + (wn * 32 + j * 16) * ASTR + kk, ASTR);
#pragma unroll
            for (int i = 0; i < 4; i++)
#pragma unroll
                for (int j = 0; j < 2; j++)
                    wmma::mma_sync(acc[i][j], af[i], bf[j], acc[i][j]);
        }
        __syncthreads();
    }

    float* Cs = reinterpret_cast<float*>(smem);
#pragma unroll
    for (int i = 0; i < 4; i++)
#pragma unroll
        for (int j = 0; j < 2; j++)
            wmma::store_matrix_sync(Cs + (wm * 64 + i * 16) * PCSTR + wn * 32 + j * 16,
                                    acc[i][j], PCSTR, wmma::mem_row_major);
    __syncthreads();

    // Epilogue: bias + RoPE + transposed store (128 x 256 = one full head wide)
#pragma unroll 4
    for (int i = 0; i < 32; i++) {
        int it = tid + i * PNT;          // 0..16383 over 128x128 pairs
        int r = it >> 7;                 // 0..127
        int pc = it & 127;               // pair col 0..127
        int c = pc << 1;
        int m = m0 + r, f = n0 + c;
        float v0 = Cs[r * PCSTR + c] + bias[f];
        float v1 = Cs[r * PCSTR + c + 1] + bias[f + 1];
        int d = f & 255;
        if (d < Rr) {
            int pos = posids[m];
            int i2 = d >> 1;
            float sn = embed[pos * Rr + i2];
            float co = embed[pos * Rr + 32 + i2];
            float o0 = v0 * co - v1 * sn;
            float o1 = v1 * co + v0 * sn;
            v0 = o0; v1 = o1;
        }
        int b_ = m >> 11, s_ = m & 2047, h_ = f >> 8;
        size_t off = ((size_t)(b_ * Hh + h_) * Ss + s_) * Dd + d;
        *reinterpret_cast<float2*>(outp + off) = make_float2(v0, v1);
        *reinterpret_cast<__half2*>(routp + off) = __floats2half2_rn(v0, v1);
    }
}

// ---------------------------------------------------------------------------
// Scores GEMM: CTA 128x128, 256 threads, 2-stage, causal tile skip (R9 winner)
// ---------------------------------------------------------------------------
__device__ __forceinline__ void s_load_chunk(uint32_t sb, const char* Ab, const char* Bbp,
                                             int kc, int buf, int tid) {
    uint32_t stA = sb + buf * S_STAGE;
    uint32_t stB = stA + S_STAGE_A;
    const char* Ap = Ab + (size_t)kc * (BK * 2);
    const char* Bp = Bbp + (size_t)kc * (BK * 2);
#pragma unroll
    for (int l = 0; l < 4; l++) {
        int idx = tid + l * SNT;
        int r = idx >> 3, cb = (idx & 7) << 4;
        cp16(stA + r * (ASTR * 2) + cb, Ap + (size_t)r * (Dd * 2) + cb);
        cp16(stB + r * (ASTR * 2) + cb, Bp + (size_t)r * (Dd * 2) + cb);
    }
}

__global__ void __launch_bounds__(SNT, 2) scores_cp_kernel(float* __restrict__ attn)
{
    int kt = blockIdx.x, qt = blockIdx.y, bh = blockIdx.z;
    if (kt > qt) return;

    extern __shared__ __align__(128) char smem[];
    uint32_t sb = smem_u32(smem);
    int m0 = qt * BM, n0 = kt * SBN;
    const char* Ab = reinterpret_cast<const char*>(g_qr + (size_t)bh * Ss * Dd + (size_t)m0 * Dd);
    const char* Bbp = reinterpret_cast<const char*>(g_kr + (size_t)bh * Ss * Dd + (size_t)n0 * Dd);
    int tid = threadIdx.x;
    int warp = tid >> 5;
    int wm = warp & 1;
    int wn = warp >> 1;

    AccFrag acc[4][2];
#pragma unroll
    for (int i = 0; i < 4; i++)
#pragma unroll
        for (int j = 0; j < 2; j++)
            wmma::fill_fragment(acc[i][j], 0.f);

    s_load_chunk(sb, Ab, Bbp, 0, 0, tid);
    CP_COMMIT();

    constexpr int NCHUNK = Dd / BK;   // 4
#pragma unroll
    for (int k = 0; k < NCHUNK; k++) {
        if (k + 1 < NCHUNK) s_load_chunk(sb, Ab, Bbp, k + 1, (k + 1) & 1, tid);
        CP_COMMIT();
        CP_WAIT1();
        __syncthreads();

        __half* As = reinterpret_cast<__half*>(smem + (k & 1) * S_STAGE);
        __half* Bs = As + BM * ASTR;
#pragma unroll
        for (int kk = 0; kk < BK; kk += 16) {
            AFrag af[4];
            BFrag bf[2];
#pragma unroll
            for (int i = 0; i < 4; i++)
                wmma::load_matrix_sync(af[i], As + (wm * 64 + i * 16) * ASTR + kk, ASTR);
#pragma unroll
            for (int j = 0; j < 2; j++)
                wmma::load_matrix_sync(bf[j], Bs + (wn * 32 + j * 16) * ASTR + kk, ASTR);
#pragma unroll
            for (int i = 0; i < 4; i++)
#pragma unroll
                for (int j = 0; j < 2; j++)
                    wmma::mma_sync(acc[i][j], af[i], bf[j], acc[i][j]);
        }
        __syncthreads();
    }

    float* Cs = reinterpret_cast<float*>(smem);
#pragma unroll
    for (int i = 0; i < 4; i++)
#pragma unroll
        for (int j = 0; j < 2; j++)
            wmma::store_matrix_sync(Cs + (wm * 64 + i * 16) * SCSTR + wn * 32 + j * 16,
                                    acc[i][j], SCSTR, wmma::mem_row_major);
    __syncthreads();

    float* out_base = attn + (size_t)bh * Ss * Ss;
#pragma unroll
    for (int i = 0; i < 16; i++) {
        int it = tid + i * SNT;            // 0..4095 float4s over 128x128
        int r = it >> 5;
        int c4 = (it & 31) << 2;
        float4 v = *reinterpret_cast<const float4*>(Cs + r * SCSTR + c4);
        v.x *= 0.0625f; v.y *= 0.0625f; v.z *= 0.0625f; v.w *= 0.0625f;
        *reinterpret_cast<float4*>(out_base + (size_t)(m0 + r) * Ss + n0 + c4) = v;
    }
}

// ---------------------------------------------------------------------------
// In-place masked softmax, float4 vectorized
// ---------------------------------------------------------------------------
__global__ void __launch_bounds__(256) softmax_kernel(float* __restrict__ attn) {
    int row = blockIdx.x;
    int q = row & 2047;
    int nv = q + 1;
    float* rowp = attn + (size_t)row * Ss;
    int tid = threadIdx.x;

    float4 vals[2];
    float mx = -INFINITY;
#pragma unroll
    for (int j = 0; j < 2; j++) {
        int k4 = (tid + j * 256) << 2;
        float4 v;
        if (k4 + 3 < nv) {
            v = *reinterpret_cast<const float4*>(rowp + k4);
        } else {
            v.x = (k4 + 0 < nv) ? rowp[k4 + 0] : -INFINITY;
            v.y = (k4 + 1 < nv) ? rowp[k4 + 1] : -INFINITY;
            v.z = (k4 + 2 < nv) ? rowp[k4 + 2] : -INFINITY;
            v.w = (k4 + 3 < nv) ? rowp[k4 + 3] : -INFINITY;
        }
        vals[j] = v;
        mx = fmaxf(mx, fmaxf(fmaxf(v.x, v.y), fmaxf(v.z, v.w)));
    }
    __shared__ float sh[8];
#pragma unroll
    for (int o = 16; o; o >>= 1) mx = fmaxf(mx, __shfl_xor_sync(~0u, mx, o));
    if ((tid & 31) == 0) sh[tid >> 5] = mx;
    __syncthreads();
    if (tid < 32) {
        float t = (tid < 8) ? sh[tid] : -INFINITY;
#pragma unroll
        for (int o = 4; o; o >>= 1) t = fmaxf(t, __shfl_xor_sync(~0u, t, o));
        if (tid == 0) sh[0] = t;
    }
    __syncthreads();
    float M = sh[0];
    __syncthreads();

    float sum = 0.f;
#pragma unroll
    for (int j = 0; j < 2; j++) {
        float4 v = vals[j];
        v.x = (v.x == -INFINITY) ? 0.f : expf(v.x - M);
        v.y = (v.y == -INFINITY) ? 0.f : expf(v.y - M);
        v.z = (v.z == -INFINITY) ? 0.f : expf(v.z - M);
        v.w = (v.w == -INFINITY) ? 0.f : expf(v.w - M);
        vals[j] = v;
        sum += v.x + v.y + v.z + v.w;
    }
#pragma unroll
    for (int o = 16; o; o >>= 1) sum += __shfl_xor_sync(~0u, sum, o);
    if ((tid & 31) == 0) sh[tid >> 5] = sum;
    __syncthreads();
    if (tid < 32) {
        float t = (tid < 8) ? sh[tid] : 0.f;
#pragma unroll
        for (int o = 4; o; o >>= 1) t += __shfl_xor_sync(~0u, t, o);
        if (tid == 0) sh[0] = t;
    }
    __syncthreads();
    float inv = 1.0f / sh[0];
#pragma unroll
    for (int j = 0; j < 2; j++) {
        int k4 = (tid + j * 256) << 2;
        float4 v = vals[j];
        v.x *= inv; v.y *= inv; v.z *= inv; v.w *= inv;
        *reinterpret_cast<float4*>(rowp + k4) = v;
    }
}

// ---------------------------------------------------------------------------
extern "C" void kernel_launch(void* const* d_in, const int* in_sizes, int n_in,
                              void* d_out, int out_size) {
    const float* x     = (const float*)d_in[0];
    const float* q_w   = (const float*)d_in[1];
    const float* q_b   = (const float*)d_in[2];
    const float* k_w   = (const float*)d_in[3];
    const float* k_b   = (const float*)d_in[4];
    const float* ln_w  = (const float*)d_in[5];
    const float* ln_b  = (const float*)d_in[6];
    const float* embed = (const float*)d_in[7];
    const int*   pos   = (const int*)d_in[8];

    float* out   = (float*)d_out;
    float* q_out = out;
    float* k_out = out + QK_ELEMS;
    float* attn  = out + 2 * QK_ELEMS;

    cudaFuncSetAttribute(proj_cp_kernel, cudaFuncAttributeMaxDynamicSharedMemorySize, (int)PROJ_SMEM);
    cudaFuncSetAttribute(scores_cp_kernel, cudaFuncAttributeMaxDynamicSharedMemorySize, (int)SCORES_SMEM);

    ln_kernel<<<Mtot, 256>>>(x, ln_w, ln_b);

    dim3 gw((unsigned)(((size_t)Ee * Ee) / 1024), 2);   // 16384 x 2
    wconv_kernel<<<gw, 256>>>(q_w, k_w);

    dim3 gp(Mtot / BM, Ee / PBN, 2);         // (32, 16, 2), x over M
    proj_cp_kernel<<<gp, PNT, PROJ_SMEM>>>(q_b, k_b, embed, pos, q_out, k_out);

    dim3 g2(Ss / SBN, Ss / BM, Bb * Hh);     // (16, 16, 32)
    scores_cp_kernel<<<g2, SNT, SCORES_SMEM>>>(attn);

    softmax_kernel<<<Bb * Hh * Ss, 256>>>(attn);
}

// round 11
// speedup vs baseline: 1.1262x; 1.1262x over previous
#include <cuda_runtime.h>
#include <mma.h>
#include <cuda_fp16.h>
#include <cstdint>
#include <math.h>

using namespace nvcuda;

// Problem constants
constexpr int Bb = 2, Ss = 2048, Ee = 4096, Hh = 16, Dd = 256, Rr = 64;
constexpr int Mtot = Bb * Ss;                  // 4096
constexpr size_t QK_ELEMS = (size_t)Bb * Hh * Ss * Dd;   // 16777216

// GEMM tiling: CTA 128x128, 8 warps (2x4), warp tile 64x32, fp16, 3-stage pipe
constexpr int BM = 128, BN = 128, BK = 64;     // BK=64 halves = 128 bytes/row
constexpr int NTHREADS = 256;
constexpr int ASTR = BK + 8;                   // 72 halves = 144 B/row
constexpr uint32_t STAGE_A_BYTES = BM * ASTR * 2;        // 18432
constexpr uint32_t STAGE_BYTES = 2 * STAGE_A_BYTES;      // 36864
constexpr int NSTAGE = 3;
constexpr int CSTR = BN + 4;                   // 132
constexpr uint32_t GEMM_SMEM = NSTAGE * STAGE_BYTES;     // 110592 (Cs 67584 fits; 2 CTAs/SM)

// Scratch (fp16 GEMM operands)
__device__ __half g_xnorm[(size_t)Mtot * Ee];
__device__ __half g_wq[(size_t)Ee * Ee];
__device__ __half g_wk[(size_t)Ee * Ee];
__device__ __half g_qr[QK_ELEMS];
__device__ __half g_kr[QK_ELEMS];

__device__ __forceinline__ uint32_t smem_u32(const void* p) {
    uint32_t a;
    asm("{ .reg .u64 t; cvta.to.shared.u64 t, %1; cvt.u32.u64 %0, t; }" : "=r"(a) : "l"(p));
    return a;
}
__device__ __forceinline__ void cp16(uint32_t dst, const void* src) {
    asm volatile("cp.async.cg.shared.global [%0], [%1], 16;" :: "r"(dst), "l"(src));
}
#define CP_COMMIT() asm volatile("cp.async.commit_group;" ::: "memory")
#define CP_WAIT2()  asm volatile("cp.async.wait_group 2;" ::: "memory")

using AccFrag = wmma::fragment<wmma::accumulator, 16, 16, 16, float>;
using AFrag = wmma::fragment<wmma::matrix_a, 16, 16, 16, __half, wmma::row_major>;
using BFrag = wmma::fragment<wmma::matrix_b, 16, 16, 16, __half, wmma::col_major>;

// ---------------------------------------------------------------------------
// LayerNorm -> fp16 g_xnorm
// ---------------------------------------------------------------------------
__global__ void __launch_bounds__(256) ln_kernel(const float* __restrict__ x,
                                                 const float* __restrict__ w,
                                                 const float* __restrict__ b) {
    int row = blockIdx.x;
    int tid = threadIdx.x;
    const float4* xr = reinterpret_cast<const float4*>(x + (size_t)row * Ee);

    float4 v[4];
    float sum = 0.f, ssq = 0.f;
#pragma unroll
    for (int j = 0; j < 4; j++) {
        v[j] = xr[tid + j * 256];
        sum += v[j].x + v[j].y + v[j].z + v[j].w;
        ssq += v[j].x * v[j].x + v[j].y * v[j].y + v[j].z * v[j].z + v[j].w * v[j].w;
    }
    __shared__ float s_sum[8], s_ssq[8];
#pragma unroll
    for (int o = 16; o; o >>= 1) {
        sum += __shfl_xor_sync(~0u, sum, o);
        ssq += __shfl_xor_sync(~0u, ssq, o);
    }
    if ((tid & 31) == 0) { s_sum[tid >> 5] = sum; s_ssq[tid >> 5] = ssq; }
    __syncthreads();
    if (tid < 32) {
        float ts = (tid < 8) ? s_sum[tid] : 0.f;
        float tq = (tid < 8) ? s_ssq[tid] : 0.f;
#pragma unroll
        for (int o = 4; o; o >>= 1) {
            ts += __shfl_xor_sync(~0u, ts, o);
            tq += __shfl_xor_sync(~0u, tq, o);
        }
        if (tid == 0) { s_sum[0] = ts; s_ssq[0] = tq; }
    }
    __syncthreads();
    float mean = s_sum[0] * (1.0f / Ee);
    float var = s_ssq[0] * (1.0f / Ee) - mean * mean;
    float rstd = rsqrtf(var + 1e-5f);

    const float4* wr = reinterpret_cast<const float4*>(w);
    const float4* br = reinterpret_cast<const float4*>(b);
    __half2* outr = reinterpret_cast<__half2*>(g_xnorm + (size_t)row * Ee);
#pragma unroll
    for (int j = 0; j < 4; j++) {
        int c = tid + j * 256;
        float4 wv = wr[c], bv = br[c];
        float o0 = (v[j].x - mean) * rstd * wv.x + bv.x;
        float o1 = (v[j].y - mean) * rstd * wv.y + bv.y;
        float o2 = (v[j].z - mean) * rstd * wv.z + bv.z;
        float o3 = (v[j].w - mean) * rstd * wv.w + bv.w;
        outr[c * 2]     = __floats2half2_rn(o0, o1);
        outr[c * 2 + 1] = __floats2half2_rn(o2, o3);
    }
}

// ---------------------------------------------------------------------------
// Weight conversion fp32 -> fp16
// ---------------------------------------------------------------------------
__global__ void __launch_bounds__(256) wconv_kernel(const float* __restrict__ wq,
                                                    const float* __restrict__ wk) {
    const float* src = blockIdx.y ? wk : wq;
    __half* dst = blockIdx.y ? g_wk : g_wq;
    size_t i = ((size_t)blockIdx.x * 256 + threadIdx.x) * 4;
    float4 v = *reinterpret_cast<const float4*>(src + i);
    __half2* d2 = reinterpret_cast<__half2*>(dst + i);
    d2[0] = __floats2half2_rn(v.x, v.y);
    d2[1] = __floats2half2_rn(v.z, v.w);
}

// ---------------------------------------------------------------------------
// Pipelined fp16 wmma GEMM (NT), CTA 128x128, 8 warps, warp tile 64x32
// 3-stage cp.async pipeline, 2 CTAs/SM
// ---------------------------------------------------------------------------
__device__ __forceinline__ void load_chunk(uint32_t sb, const char* Ab, const char* Bbp,
                                           size_t ldab, int kc, int buf, int tid) {
    uint32_t stA = sb + buf * STAGE_BYTES;
    uint32_t stB = stA + STAGE_A_BYTES;
    const char* Ap = Ab + (size_t)kc * (BK * 2);
    const char* Bp = Bbp + (size_t)kc * (BK * 2);
#pragma unroll
    for (int l = 0; l < 4; l++) {
        int idx = tid + l * NTHREADS;    // 0..1023
        int r = idx >> 3, cb = (idx & 7) << 4;
        cp16(stA + r * (ASTR * 2) + cb, Ap + (size_t)r * ldab + cb);
        cp16(stB + r * (ASTR * 2) + cb, Bp + (size_t)r * ldab + cb);
    }
}

template <int NCHUNK>
__device__ __forceinline__ void gemm_pipe(const char* Ab, const char* Bbp, size_t ldab,
                                          char* smem, AccFrag acc[4][2]) {
    uint32_t sb = smem_u32(smem);
    int tid = threadIdx.x;
    int warp = tid >> 5;
    int wm = warp & 1;        // 2 along M, 64 rows each
    int wn = warp >> 1;       // 4 along N, 32 cols each

    load_chunk(sb, Ab, Bbp, ldab, 0, 0, tid);
    CP_COMMIT();
    if (NCHUNK > 1) load_chunk(sb, Ab, Bbp, ldab, 1, 1, tid);
    CP_COMMIT();

    for (int k = 0; k < NCHUNK; k++) {
        if (k + 2 < NCHUNK) load_chunk(sb, Ab, Bbp, ldab, k + 2, (k + 2) % NSTAGE, tid);
        CP_COMMIT();
        CP_WAIT2();               // chunk k resident; k+1, k+2 may still fly
        __syncthreads();

        __half* As = reinterpret_cast<__half*>(smem + (k % NSTAGE) * STAGE_BYTES);
        __half* Bs = As + BM * ASTR;
#pragma unroll
        for (int kk = 0; kk < BK; kk += 16) {
            AFrag af[4];
            BFrag bf[2];
#pragma unroll
            for (int i = 0; i < 4; i++)
                wmma::load_matrix_sync(af[i], As + (wm * 64 + i * 16) * ASTR + kk, ASTR);
#pragma unroll
            for (int j = 0; j < 2; j++)
                wmma::load_matrix_sync(bf[j], Bs + (wn * 32 + j * 16) * ASTR + kk, ASTR);
#pragma unroll
            for (int i = 0; i < 4; i++)
#pragma unroll
                for (int j = 0; j < 2; j++)
                    wmma::mma_sync(acc[i][j], af[i], bf[j], acc[i][j]);
        }
        __syncthreads();
    }
}

__device__ __forceinline__ void store_acc(float* Cs, AccFrag acc[4][2]) {
    int warp = threadIdx.x >> 5;
    int wm = warp & 1, wn = warp >> 1;
#pragma unroll
    for (int i = 0; i < 4; i++)
#pragma unroll
        for (int j = 0; j < 2; j++)
            wmma::store_matrix_sync(Cs + (wm * 64 + i * 16) * CSTR + wn * 32 + j * 16,
                                    acc[i][j], CSTR, wmma::mem_row_major);
}

// ---------------------------------------------------------------------------
// Projection GEMM + bias + RoPE; fp32 q/k to d_out, fp16 copies for scores
// ---------------------------------------------------------------------------
__global__ void __launch_bounds__(NTHREADS, 2) proj_cp_kernel(
    const float* __restrict__ bq, const float* __restrict__ bk,
    const float* __restrict__ embed, const int* __restrict__ posids,
    float* __restrict__ qout, float* __restrict__ kout)
{
    extern __shared__ __align__(128) char smem[];
    int z = blockIdx.z;
    const __half* W   = z ? g_wk : g_wq;
    const float* bias = z ? bk : bq;
    float* outp       = z ? kout : qout;
    __half* routp     = z ? g_kr : g_qr;
    const int m0 = blockIdx.x * BM;   // x fastest: consecutive CTAs share the weight panel
    const int n0 = blockIdx.y * BN;

    AccFrag acc[4][2];
#pragma unroll
    for (int i = 0; i < 4; i++)
#pragma unroll
        for (int j = 0; j < 2; j++)
            wmma::fill_fragment(acc[i][j], 0.f);

    gemm_pipe<Ee / BK>(reinterpret_cast<const char*>(g_xnorm + (size_t)m0 * Ee),
                       reinterpret_cast<const char*>(W + (size_t)n0 * Ee),
                       (size_t)Ee * 2, smem, acc);

    float* Cs = reinterpret_cast<float*>(smem);
    store_acc(Cs, acc);
    __syncthreads();

    int tid = threadIdx.x;
#pragma unroll 4
    for (int i = 0; i < 32; i++) {
        int it = tid + i * NTHREADS;     // 0..8191 over 128x64 pairs
        int r = it >> 6;                 // 0..127
        int pc = it & 63;
        int c = pc << 1;
        int m = m0 + r, f = n0 + c;
        float v0 = Cs[r * CSTR + c] + bias[f];
        float v1 = Cs[r * CSTR + c + 1] + bias[f + 1];
        int d = f & 255;
        if (d < Rr) {
            int pos = posids[m];
            int i2 = d >> 1;
            float sn = embed[pos * Rr + i2];
            float co = embed[pos * Rr + 32 + i2];
            float o0 = v0 * co - v1 * sn;
            float o1 = v1 * co + v0 * sn;
            v0 = o0; v1 = o1;
        }
        int b_ = m >> 11, s_ = m & 2047, h_ = f >> 8;
        size_t off = ((size_t)(b_ * Hh + h_) * Ss + s_) * Dd + d;
        *reinterpret_cast<float2*>(outp + off) = make_float2(v0, v1);
        *reinterpret_cast<__half2*>(routp + off) = __floats2half2_rn(v0, v1);
    }
}

// ---------------------------------------------------------------------------
// Scores GEMM: scores = Qh.Kh^T / 16, causal tile skip
// ---------------------------------------------------------------------------
__global__ void __launch_bounds__(NTHREADS, 2) scores_cp_kernel(float* __restrict__ attn)
{
    int kt = blockIdx.x, qt = blockIdx.y, bh = blockIdx.z;
    if (kt > qt) return;

    extern __shared__ __align__(128) char smem[];
    int m0 = qt * BM, n0 = kt * BN;
    const __half* Q = g_qr + (size_t)bh * Ss * Dd;
    const __half* Kv = g_kr + (size_t)bh * Ss * Dd;

    AccFrag acc[4][2];
#pragma unroll
    for (int i = 0; i < 4; i++)
#pragma unroll
        for (int j = 0; j < 2; j++)
            wmma::fill_fragment(acc[i][j], 0.f);

    gemm_pipe<Dd / BK>(reinterpret_cast<const char*>(Q + (size_t)m0 * Dd),
                       reinterpret_cast<const char*>(Kv + (size_t)n0 * Dd),
                       (size_t)Dd * 2, smem, acc);

    float* Cs = reinterpret_cast<float*>(smem);
    store_acc(Cs, acc);
    __syncthreads();

    float* out_base = attn + (size_t)bh * Ss * Ss;
#pragma unroll
    for (int i = 0; i < 16; i++) {
        int it = threadIdx.x + i * NTHREADS;   // 0..4095 float4s over 128x128
        int r = it >> 5;
        int c4 = (it & 31) << 2;
        float4 v = *reinterpret_cast<const float4*>(Cs + r * CSTR + c4);
        v.x *= 0.0625f; v.y *= 0.0625f; v.z *= 0.0625f; v.w *= 0.0625f;
        *reinterpret_cast<float4*>(out_base + (size_t)(m0 + r) * Ss + n0 + c4) = v;
    }
}

// ---------------------------------------------------------------------------
// In-place masked softmax, float4 vectorized
// ---------------------------------------------------------------------------
__global__ void __launch_bounds__(256) softmax_kernel(float* __restrict__ attn) {
    int row = blockIdx.x;
    int q = row & 2047;
    int nv = q + 1;
    float* rowp = attn + (size_t)row * Ss;
    int tid = threadIdx.x;

    float4 vals[2];
    float mx = -INFINITY;
#pragma unroll
    for (int j = 0; j < 2; j++) {
        int k4 = (tid + j * 256) << 2;
        float4 v;
        if (k4 + 3 < nv) {
            v = *reinterpret_cast<const float4*>(rowp + k4);
        } else {
            v.x = (k4 + 0 < nv) ? rowp[k4 + 0] : -INFINITY;
            v.y = (k4 + 1 < nv) ? rowp[k4 + 1] : -INFINITY;
            v.z = (k4 + 2 < nv) ? rowp[k4 + 2] : -INFINITY;
            v.w = (k4 + 3 < nv) ? rowp[k4 + 3] : -INFINITY;
        }
        vals[j] = v;
        mx = fmaxf(mx, fmaxf(fmaxf(v.x, v.y), fmaxf(v.z, v.w)));
    }
    __shared__ float sh[8];
#pragma unroll
    for (int o = 16; o; o >>= 1) mx = fmaxf(mx, __shfl_xor_sync(~0u, mx, o));
    if ((tid & 31) == 0) sh[tid >> 5] = mx;
    __syncthreads();
    if (tid < 32) {
        float t = (tid < 8) ? sh[tid] : -INFINITY;
#pragma unroll
        for (int o = 4; o; o >>= 1) t = fmaxf(t, __shfl_xor_sync(~0u, t, o));
        if (tid == 0) sh[0] = t;
    }
    __syncthreads();
    float M = sh[0];
    __syncthreads();

    float sum = 0.f;
#pragma unroll
    for (int j = 0; j < 2; j++) {
        float4 v = vals[j];
        v.x = (v.x == -INFINITY) ? 0.f : expf(v.x - M);
        v.y = (v.y == -INFINITY) ? 0.f : expf(v.y - M);
        v.z = (v.z == -INFINITY) ? 0.f : expf(v.z - M);
        v.w = (v.w == -INFINITY) ? 0.f : expf(v.w - M);
        vals[j] = v;
        sum += v.x + v.y + v.z + v.w;
    }
#pragma unroll
    for (int o = 16; o; o >>= 1) sum += __shfl_xor_sync(~0u, sum, o);
    if ((tid & 31) == 0) sh[tid >> 5] = sum;
    __syncthreads();
    if (tid < 32) {
        float t = (tid < 8) ? sh[tid] : 0.f;
#pragma unroll
        for (int o = 4; o; o >>= 1) t += __shfl_xor_sync(~0u, t, o);
        if (tid == 0) sh[0] = t;
    }
    __syncthreads();
    float inv = 1.0f / sh[0];
#pragma unroll
    for (int j = 0; j < 2; j++) {
        int k4 = (tid + j * 256) << 2;
        float4 v = vals[j];
        v.x *= inv; v.y *= inv; v.z *= inv; v.w *= inv;
        *reinterpret_cast<float4*>(rowp + k4) = v;
    }
}

// ---------------------------------------------------------------------------
extern "C" void kernel_launch(void* const* d_in, const int* in_sizes, int n_in,
                              void* d_out, int out_size) {
    const float* x     = (const float*)d_in[0];
    const float* q_w   = (const float*)d_in[1];
    const float* q_b   = (const float*)d_in[2];
    const float* k_w   = (const float*)d_in[3];
    const float* k_b   = (const float*)d_in[4];
    const float* ln_w  = (const float*)d_in[5];
    const float* ln_b  = (const float*)d_in[6];
    const float* embed = (const float*)d_in[7];
    const int*   pos   = (const int*)d_in[8];

    float* out   = (float*)d_out;
    float* q_out = out;
    float* k_out = out + QK_ELEMS;
    float* attn  = out + 2 * QK_ELEMS;

    cudaFuncSetAttribute(proj_cp_kernel, cudaFuncAttributeMaxDynamicSharedMemorySize, (int)GEMM_SMEM);
    cudaFuncSetAttribute(scores_cp_kernel, cudaFuncAttributeMaxDynamicSharedMemorySize, (int)GEMM_SMEM);

    ln_kernel<<<Mtot, 256>>>(x, ln_w, ln_b);

    dim3 gw((unsigned)(((size_t)Ee * Ee) / 1024), 2);   // 16384 x 2
    wconv_kernel<<<gw, 256>>>(q_w, k_w);

    dim3 gp(Mtot / BM, Ee / BN, 2);          // (32, 32, 2), x over M
    proj_cp_kernel<<<gp, NTHREADS, GEMM_SMEM>>>(q_b, k_b, embed, pos, q_out, k_out);

    dim3 g2(Ss / BN, Ss / BM, Bb * Hh);      // (16, 16, 32)
    scores_cp_kernel<<<g2, NTHREADS, GEMM_SMEM>>>(attn);

    softmax_kernel<<<Bb * Hh * Ss, 256>>>(attn);
}